// round 7
// baseline (speedup 1.0000x reference)
#include <cuda_runtime.h>
#include <cuda_fp16.h>
#include <cstdint>

// ===========================================================================
// SSRupsampling via HMMA (mma.sync m16n8k16, fp32 accum), fp16 3-product
// split. Conv B = shifted view of compact [pix,512] act. 256x128 block tile,
// 64x64 warp tiles. Pixel shuffles fused into GEMM epilogues.
// ===========================================================================

// ------------------------------ scratch -----------------------------------
__device__ __half g_aHi[36864L * 512], g_aLo[36864L * 512];
__device__ __half g_bHi[36864L * 512], g_bLo[36864L * 512];
__device__ __half g_cHi[18432 * 512],  g_cLo[18432 * 512];
__device__ __half g_B2hi[9216 * 512],  g_B2lo[9216 * 512];
__device__ __half g_wch_hi[512 * 2048], g_wch_lo[512 * 2048];
__device__ __half g_ww_hi[1024 * 512],  g_ww_lo[1024 * 512];
__device__ __half g_wH_hi[1024 * 512],  g_wH_lo[1024 * 512];
__device__ __half g_wlr_hi[512 * 4608], g_wlr_lo[512 * 4608];
__device__ __half g_wdu_hi[512 * 4608], g_wdu_lo[512 * 4608];

// ------------------------------ helpers -----------------------------------
__device__ __forceinline__ uint32_t smem_u32(const void* p) {
    uint32_t a;
    asm("{ .reg .u64 t; cvta.to.shared.u64 t, %1; cvt.u32.u64 %0, t; }"
        : "=r"(a) : "l"(p));
    return a;
}
__device__ __forceinline__ void ldsm_x4(uint32_t* r, uint32_t addr) {
    asm volatile("ldmatrix.sync.aligned.m8n8.x4.shared.b16 {%0,%1,%2,%3}, [%4];"
                 : "=r"(r[0]), "=r"(r[1]), "=r"(r[2]), "=r"(r[3]) : "r"(addr));
}
__device__ __forceinline__ void mma16816(float* c, const uint32_t* a,
                                         const uint32_t* b) {
    asm volatile(
        "mma.sync.aligned.m16n8k16.row.col.f32.f16.f16.f32 "
        "{%0,%1,%2,%3}, {%4,%5,%6,%7}, {%8,%9}, {%0,%1,%2,%3};"
        : "+f"(c[0]), "+f"(c[1]), "+f"(c[2]), "+f"(c[3])
        : "r"(a[0]), "r"(a[1]), "r"(a[2]), "r"(a[3]), "r"(b[0]), "r"(b[1]));
}
__device__ __forceinline__ void cp16(uint32_t sa, const void* ga) {
    asm volatile("cp.async.cg.shared.global [%0], [%1], 16;"
                 :: "r"(sa), "l"(ga));
}
__device__ __forceinline__ void cp16p(uint32_t sa, const void* ga, int sz) {
    asm volatile("cp.async.cg.shared.global [%0], [%1], 16, %2;"
                 :: "r"(sa), "l"(ga), "r"(sz));
}

#define BK 32
#define PITCH 80
#define A_BYTES (256 * PITCH)     // 20480 per operand half
#define B_BYTES (128 * PITCH)     // 10240 per operand half
#define OFF_AHI 0
#define OFF_ALO A_BYTES
#define OFF_BHI (2 * A_BYTES)
#define OFF_BLO (2 * A_BYTES + B_BYTES)
#define STAGE_BYTES (2 * A_BYTES + 2 * B_BYTES)   // 61440
#define SMEM_TOTAL (2 * STAGE_BYTES)              // 122880

__device__ __forceinline__ void split_g(float v, __half* hi, __half* lo,
                                        long idx) {
    __half h = __float2half_rn(v);
    hi[idx] = h;
    lo[idx] = __float2half_rn(v - __half2float(h));
}

// ---------------------------------------------------------------------------
// GEMM: D[m,n] = sum_k A[m,k]*B[n,k], fp16 x3 split, fp32 accum.
// Block tile 256(M) x 128(N), 8 warps (4m x 2n), warp tile 64x64, BK=32.
// conv!=0: K=4608 logical (9 taps x 512); B read from [Npix,512] with row
// shift (t-4) and l/s boundary mask (pix = img*288 + l*3 + s).
// Modes: 1 split [pix,512]; 3 bias+relu split [pix,512];
//        4 bias+relu NCHW scatter (final); 5 split + H-shuffle (stage2);
//        6 split + W-shuffle (w_H stage).
// ---------------------------------------------------------------------------
__global__ __launch_bounds__(256, 1)
void gemm_hmma(const __half* __restrict__ Ahi, const __half* __restrict__ Alo,
               const __half* __restrict__ Bhi, const __half* __restrict__ Blo,
               int K, int Kb, int conv, int mode,
               const float* __restrict__ bias, float* __restrict__ outF,
               __half* __restrict__ outHi, __half* __restrict__ outLo) {
    extern __shared__ char smem[];
    const uint32_t sb = smem_u32(smem);
    const int tid = threadIdx.x;
    const int lane = tid & 31, wid = tid >> 5;
    const int wm = wid >> 1, wn = wid & 1;
    const int m0 = blockIdx.x * 256;
    const long n0 = (long)blockIdx.y * 128;

    const __half* gA0 = Ahi + (long)m0 * K;
    const __half* gA1 = Alo + (long)m0 * K;
    const __half* gB0 = Bhi + n0 * Kb;
    const __half* gB1 = Blo + n0 * Kb;

    const int lrow = tid >> 2, lcol = tid & 3;   // B rows: lrow, lrow+64

    // conv B-row geometry
    int l0 = 0, s0 = 0, l1 = 0, s1 = 0;
    if (conv) {
        const int p0 = (int)n0 + lrow, p1 = p0 + 64;
        s0 = p0 % 3; l0 = (p0 / 3) % 96;
        s1 = p1 % 3; l1 = (p1 / 3) % 96;
    }

    const int lg = lane >> 3, lr = lane & 7;
    const uint32_t aoff = (uint32_t)(((lg & 1) * 8 + lr) + wm * 64) * PITCH +
                          (lg >> 1) * 16;
    const uint32_t boff = (uint32_t)(((lg >> 1) * 8 + lr) + wn * 64) * PITCH +
                          (lg & 1) * 16;

    float acc[4][8][4];
    #pragma unroll
    for (int i = 0; i < 4; i++)
        #pragma unroll
        for (int j = 0; j < 8; j++)
            #pragma unroll
            for (int c = 0; c < 4; c++) acc[i][j][c] = 0.f;

    const int nC = K / BK;

    auto issue = [&](int kc) {
        const uint32_t so = sb + (kc & 1) * STAGE_BYTES;
        // A: 256 rows x 4 cp16-cols, 4 row-iters per thread
        {
            const long kb = (long)kc * BK;
            #pragma unroll
            for (int it = 0; it < 4; it++) {
                const int row = lrow + it * 64;
                const uint32_t sa = so + row * PITCH + lcol * 16;
                const long ga = (long)row * K + kb + lcol * 8;
                cp16(sa + OFF_AHI, gA0 + ga);
                cp16(sa + OFF_ALO, gA1 + ga);
            }
        }
        // B: 128 rows, 2 row-iters per thread
        const uint32_t s0a = so + lrow * PITCH + lcol * 16;
        const uint32_t s1a = so + (lrow + 64) * PITCH + lcol * 16;
        if (conv) {
            const int t = kc >> 4;
            const int dlm = t / 3 - 1, dsm = t % 3 - 1;
            const int koff = (kc & 15) * 32 + lcol * 8;
            const long rs = (long)(t - 4) * Kb;
            const int v0 = ((unsigned)(l0 + dlm) < 96u &&
                            (unsigned)(s0 + dsm) < 3u) ? 16 : 0;
            const int v1 = ((unsigned)(l1 + dlm) < 96u &&
                            (unsigned)(s1 + dsm) < 3u) ? 16 : 0;
            const long gb0 = (long)lrow * Kb + rs + koff;
            const long gb1 = (long)(lrow + 64) * Kb + rs + koff;
            cp16p(s0a + OFF_BHI, gB0 + gb0, v0);
            cp16p(s1a + OFF_BHI, gB0 + gb1, v1);
            cp16p(s0a + OFF_BLO, gB1 + gb0, v0);
            cp16p(s1a + OFF_BLO, gB1 + gb1, v1);
        } else {
            const long kb = (long)kc * BK;
            const long gb0 = (long)lrow * Kb + kb + lcol * 8;
            const long gb1 = (long)(lrow + 64) * Kb + kb + lcol * 8;
            cp16(s0a + OFF_BHI, gB0 + gb0);
            cp16(s1a + OFF_BHI, gB0 + gb1);
            cp16(s0a + OFF_BLO, gB1 + gb0);
            cp16(s1a + OFF_BLO, gB1 + gb1);
        }
        asm volatile("cp.async.commit_group;" ::: "memory");
    };

    issue(0);
    for (int kc = 0; kc < nC; kc++) {
        if (kc + 1 < nC) {
            issue(kc + 1);
            asm volatile("cp.async.wait_group 1;" ::: "memory");
        } else {
            asm volatile("cp.async.wait_group 0;" ::: "memory");
        }
        __syncthreads();

        const uint32_t so = sb + (kc & 1) * STAGE_BYTES;
        #pragma unroll
        for (int ks = 0; ks < 2; ks++) {
            uint32_t ah[4][4], al[4][4];
            const uint32_t ab = so + aoff + ks * 32;
            #pragma unroll
            for (int mi = 0; mi < 4; mi++) {
                ldsm_x4(ah[mi], ab + mi * 16 * PITCH);
                ldsm_x4(al[mi], ab + OFF_ALO + mi * 16 * PITCH);
            }
            const uint32_t bb = so + OFF_BHI + boff + ks * 32;
            #pragma unroll
            for (int p = 0; p < 4; p++) {
                uint32_t bh[4], bl[4];
                ldsm_x4(bh, bb + p * 16 * PITCH);
                ldsm_x4(bl, bb + p * 16 * PITCH + B_BYTES);
                #pragma unroll
                for (int mi = 0; mi < 4; mi++) {
                    mma16816(acc[mi][2 * p],     ah[mi], bh);
                    mma16816(acc[mi][2 * p],     ah[mi], bl);
                    mma16816(acc[mi][2 * p],     al[mi], bh);
                    mma16816(acc[mi][2 * p + 1], ah[mi], bh + 2);
                    mma16816(acc[mi][2 * p + 1], ah[mi], bl + 2);
                    mma16816(acc[mi][2 * p + 1], al[mi], bh + 2);
                }
            }
        }
        __syncthreads();
    }

    // ---------------- epilogue -------------------------------------------
    const int mrow = m0 + wm * 64 + (lane >> 2);
    const int nrow = wn * 64 + 2 * (lane & 3);
    #pragma unroll
    for (int mi = 0; mi < 4; mi++) {
        #pragma unroll
        for (int nj = 0; nj < 8; nj++) {
            #pragma unroll
            for (int ci = 0; ci < 4; ci++) {
                const int m = mrow + mi * 16 + (ci >> 1) * 8;
                const long pix = n0 + nrow + nj * 8 + (ci & 1);
                float v = acc[mi][nj][ci];
                if (mode == 3 || mode == 4) v = fmaxf(v + bias[m], 0.f);
                if (mode == 1 || mode == 3) {
                    split_g(v, outHi, outLo, pix * 512 + m);
                } else if (mode == 4) {       // NCHW scatter (convDU geometry)
                    int img = (int)(pix / 288);
                    int rem = (int)(pix - (long)img * 288);
                    int l = rem / 3, s = rem - l * 3;
                    int nb = img >> 5, ck = img & 31;
                    int h = ck * 3 + s;
                    outF[(((long)nb * 512 + m) * 96 + h) * 96 + l] = v;
                } else if (mode == 5) {       // split + H-shuffle -> LR act
                    int p = (int)pix;
                    int n = p / 2304, rem = p - n * 2304;
                    int h = rem / 48, w = rem - h * 48;
                    int h2 = 2 * h + (m >> 9);
                    int ckW = w / 3, s = w - ckW * 3;
                    long pixLR = (long)(n * 16 + ckW) * 288 + h2 * 3 + s;
                    split_g(v, outHi, outLo, pixLR * 512 + (m & 511));
                } else {                      // mode 6: split + W-shuffle -> DU act
                    int p = (int)pix;
                    int img = p / 288, rem = p - img * 288;
                    int h2 = rem / 3, s = rem - h2 * 3;
                    int n = img >> 4, ckW = img & 15;
                    int w = ckW * 3 + s;
                    int w2 = 2 * w + (m >> 9);
                    int ckH = h2 / 3, sH = h2 - ckH * 3;
                    long pixDU = (long)(n * 32 + ckH) * 288 + w2 * 3 + sH;
                    split_g(v, outHi, outLo, pixDU * 512 + (m & 511));
                }
            }
        }
    }
}

// ------------------------- prep kernels -----------------------------------
__global__ void splitW(const float* __restrict__ src, __half* __restrict__ hi,
                       __half* __restrict__ lo, int count) {
    int i = blockIdx.x * 256 + threadIdx.x;
    if (i < count) split_g(src[i], hi, lo, i);
}

// conv weight reorder + split: dst[co*4608 + t*512 + ci]
__global__ void splitWConv(const float* __restrict__ w, __half* __restrict__ hi,
                           __half* __restrict__ lo, int mulL, int mulS) {
    int i = blockIdx.x * 256 + threadIdx.x;
    int ci = i & 511;
    int t = (i >> 9) % 9;
    int co = i / 4608;
    int dl = t / 3, ds = t % 3;
    float v = w[(long)co * 4608 + ci * 9 + dl * mulL + ds * mulS];
    split_g(v, hi, lo, (long)co * 4608 + t * 512 + ci);
}

// x[n,c,h,w] -> B[pix(n,h,w), c] split
__global__ void gatherX(const float* __restrict__ x, __half* __restrict__ bhi,
                        __half* __restrict__ blo) {
    int i = blockIdx.x * 256 + threadIdx.x;
    int c4 = i & 511;
    int pix = i >> 9;
    int n = pix / 2304;
    int p = pix - n * 2304;
    const float* xs = x + ((long)n * 2048 + c4 * 4) * 2304 + p;
    long o = (long)pix * 2048 + c4 * 4;
    split_g(xs[0],    bhi, blo, o + 0);
    split_g(xs[2304], bhi, blo, o + 1);
    split_g(xs[4608], bhi, blo, o + 2);
    split_g(xs[6912], bhi, blo, o + 3);
}

// ---------------------------------------------------------------------------
// kernel_launch.  Inputs: x, w_channel, w_w, w_H, w_lr, b_lr, w_du, b_du
// ---------------------------------------------------------------------------
extern "C" void kernel_launch(void* const* d_in, const int* in_sizes, int n_in,
                              void* d_out, int out_size) {
    const float* x         = (const float*)d_in[0];
    const float* w_channel = (const float*)d_in[1];
    const float* w_w       = (const float*)d_in[2];
    const float* w_H       = (const float*)d_in[3];
    const float* w_lr      = (const float*)d_in[4];
    const float* b_lr      = (const float*)d_in[5];
    const float* w_du      = (const float*)d_in[6];
    const float* b_du      = (const float*)d_in[7];
    float* out = (float*)d_out;

    __half *aHi, *aLo, *bHi, *bLo, *cHi, *cLo, *B2hi, *B2lo;
    __half *wch_hi, *wch_lo, *ww_hi, *ww_lo, *wH_hi, *wH_lo;
    __half *wlr_hi, *wlr_lo, *wdu_hi, *wdu_lo;
    cudaGetSymbolAddress((void**)&aHi, g_aHi);
    cudaGetSymbolAddress((void**)&aLo, g_aLo);
    cudaGetSymbolAddress((void**)&bHi, g_bHi);
    cudaGetSymbolAddress((void**)&bLo, g_bLo);
    cudaGetSymbolAddress((void**)&cHi, g_cHi);
    cudaGetSymbolAddress((void**)&cLo, g_cLo);
    cudaGetSymbolAddress((void**)&B2hi, g_B2hi);
    cudaGetSymbolAddress((void**)&B2lo, g_B2lo);
    cudaGetSymbolAddress((void**)&wch_hi, g_wch_hi);
    cudaGetSymbolAddress((void**)&wch_lo, g_wch_lo);
    cudaGetSymbolAddress((void**)&ww_hi, g_ww_hi);
    cudaGetSymbolAddress((void**)&ww_lo, g_ww_lo);
    cudaGetSymbolAddress((void**)&wH_hi, g_wH_hi);
    cudaGetSymbolAddress((void**)&wH_lo, g_wH_lo);
    cudaGetSymbolAddress((void**)&wlr_hi, g_wlr_hi);
    cudaGetSymbolAddress((void**)&wlr_lo, g_wlr_lo);
    cudaGetSymbolAddress((void**)&wdu_hi, g_wdu_hi);
    cudaGetSymbolAddress((void**)&wdu_lo, g_wdu_lo);

    cudaFuncSetAttribute(gemm_hmma, cudaFuncAttributeMaxDynamicSharedMemorySize,
                         SMEM_TOTAL);

    // weight prep
    splitW<<<(512 * 2048) / 256, 256>>>(w_channel, wch_hi, wch_lo, 512 * 2048);
    splitW<<<(1024 * 512) / 256, 256>>>(w_w, ww_hi, ww_lo, 1024 * 512);
    splitW<<<(1024 * 512) / 256, 256>>>(w_H, wH_hi, wH_lo, 1024 * 512);
    splitWConv<<<(512 * 4608) / 256, 256>>>(w_lr, wlr_hi, wlr_lo, 3, 1);
    splitWConv<<<(512 * 4608) / 256, 256>>>(w_du, wdu_hi, wdu_lo, 1, 3);

    // stage 1: split(x) -> a [9216,2048]; y1 = w_channel @ x -> split B2
    gatherX<<<(9216 * 512) / 256, 256>>>(x, aHi, aLo);
    gemm_hmma<<<dim3(2, 72), 256, SMEM_TOTAL>>>(
        wch_hi, wch_lo, aHi, aLo, 2048, 2048, 0, 1, nullptr,
        nullptr, B2hi, B2lo);

    // stage 2: w_w @ y1, epilogue = H-shuffle + split -> LR act b [18432,512]
    gemm_hmma<<<dim3(4, 72), 256, SMEM_TOTAL>>>(
        ww_hi, ww_lo, B2hi, B2lo, 512, 512, 0, 5, nullptr,
        nullptr, bHi, bLo);

    // convLR pass 1 -> split c [18432,512]
    gemm_hmma<<<dim3(2, 144), 256, SMEM_TOTAL>>>(
        wlr_hi, wlr_lo, bHi, bLo, 4608, 512, 1, 3, b_lr,
        nullptr, cHi, cLo);

    // convLR pass 2 -> split a [18432,512]
    gemm_hmma<<<dim3(2, 144), 256, SMEM_TOTAL>>>(
        wlr_hi, wlr_lo, cHi, cLo, 4608, 512, 1, 3, b_lr,
        nullptr, aHi, aLo);

    // w_H stage: epilogue = W-shuffle + split -> DU act b [36864,512]
    gemm_hmma<<<dim3(4, 144), 256, SMEM_TOTAL>>>(
        wH_hi, wH_lo, aHi, aLo, 512, 512, 0, 6, nullptr,
        nullptr, bHi, bLo);

    // convDU pass 1 -> split a [36864,512]
    gemm_hmma<<<dim3(2, 288), 256, SMEM_TOTAL>>>(
        wdu_hi, wdu_lo, bHi, bLo, 4608, 512, 1, 3, b_du,
        nullptr, aHi, aLo);

    // convDU pass 2 -> final NCHW output
    gemm_hmma<<<dim3(2, 288), 256, SMEM_TOTAL>>>(
        wdu_hi, wdu_lo, aHi, aLo, 4608, 512, 1, 4, b_du,
        out, nullptr, nullptr);
}

// round 8
// speedup vs baseline: 1.0561x; 1.0561x over previous
#include <cuda_runtime.h>
#include <cuda_fp16.h>
#include <cstdint>

// ===========================================================================
// SSRupsampling via HMMA (mma.sync m16n8k16, fp32 accum), fp16 3-product
// split. Conv B = shifted view of compact [pix,512] act (no im2col).
// GEMM: 128x128 block tile, 32x64 warp tile, 2 CTA/SM (R5 known-good core).
// Pixel shuffles fused into GEMM epilogues (R6 validated math).
// ===========================================================================

// ------------------------------ scratch -----------------------------------
__device__ __half g_aHi[36864L * 512], g_aLo[36864L * 512];
__device__ __half g_bHi[36864L * 512], g_bLo[36864L * 512];
__device__ __half g_cHi[18432 * 512],  g_cLo[18432 * 512];
__device__ __half g_B2hi[9216 * 512],  g_B2lo[9216 * 512];
__device__ __half g_wch_hi[512 * 2048], g_wch_lo[512 * 2048];
__device__ __half g_ww_hi[1024 * 512],  g_ww_lo[1024 * 512];
__device__ __half g_wH_hi[1024 * 512],  g_wH_lo[1024 * 512];
__device__ __half g_wlr_hi[512 * 4608], g_wlr_lo[512 * 4608];
__device__ __half g_wdu_hi[512 * 4608], g_wdu_lo[512 * 4608];

// ------------------------------ helpers -----------------------------------
__device__ __forceinline__ uint32_t smem_u32(const void* p) {
    uint32_t a;
    asm("{ .reg .u64 t; cvta.to.shared.u64 t, %1; cvt.u32.u64 %0, t; }"
        : "=r"(a) : "l"(p));
    return a;
}
__device__ __forceinline__ void ldsm_x4(uint32_t* r, uint32_t addr) {
    asm volatile("ldmatrix.sync.aligned.m8n8.x4.shared.b16 {%0,%1,%2,%3}, [%4];"
                 : "=r"(r[0]), "=r"(r[1]), "=r"(r[2]), "=r"(r[3]) : "r"(addr));
}
__device__ __forceinline__ void mma16816(float* c, const uint32_t* a,
                                         const uint32_t* b) {
    asm volatile(
        "mma.sync.aligned.m16n8k16.row.col.f32.f16.f16.f32 "
        "{%0,%1,%2,%3}, {%4,%5,%6,%7}, {%8,%9}, {%0,%1,%2,%3};"
        : "+f"(c[0]), "+f"(c[1]), "+f"(c[2]), "+f"(c[3])
        : "r"(a[0]), "r"(a[1]), "r"(a[2]), "r"(a[3]), "r"(b[0]), "r"(b[1]));
}
__device__ __forceinline__ void cp16(uint32_t sa, const void* ga) {
    asm volatile("cp.async.cg.shared.global [%0], [%1], 16;"
                 :: "r"(sa), "l"(ga));
}
__device__ __forceinline__ void cp16p(uint32_t sa, const void* ga, int sz) {
    asm volatile("cp.async.cg.shared.global [%0], [%1], 16, %2;"
                 :: "r"(sa), "l"(ga), "r"(sz));
}

#define BK 32
#define PITCH 80
#define TILE_BYTES (128 * PITCH)
#define STAGE_BYTES (4 * TILE_BYTES)
#define SMEM_TOTAL (2 * STAGE_BYTES)   // 81920

__device__ __forceinline__ void split_g(float v, __half* hi, __half* lo,
                                        long idx) {
    __half h = __float2half_rn(v);
    hi[idx] = h;
    lo[idx] = __float2half_rn(v - __half2float(h));
}

// ---------------------------------------------------------------------------
// GEMM: D[m,n] = sum_k A[m,k]*B[n,k], fp16 x3 split, fp32 accum.
// Block tile 128x128, BK=32, 256 threads (8 warps, 4m x 2n), warp tile 32x64.
// conv!=0: K=4608 logical (9 taps x 512); B read from [Npix,512] with row
// shift (t-4) and l/s boundary mask (pix = img*288 + l*3 + s).
// Modes: 1 split [pix,512]; 3 bias+relu split [pix,512];
//        4 bias+relu NCHW scatter (final); 5 split + H-shuffle (stage2);
//        6 split + W-shuffle (w_H stage).
// ---------------------------------------------------------------------------
__global__ __launch_bounds__(256, 2)
void gemm_hmma(const __half* __restrict__ Ahi, const __half* __restrict__ Alo,
               const __half* __restrict__ Bhi, const __half* __restrict__ Blo,
               int K, int Kb, int conv, int mode,
               const float* __restrict__ bias, float* __restrict__ outF,
               __half* __restrict__ outHi, __half* __restrict__ outLo) {
    extern __shared__ char smem[];
    const uint32_t sb = smem_u32(smem);
    const int tid = threadIdx.x;
    const int lane = tid & 31, wid = tid >> 5;
    const int wm = wid >> 1, wn = wid & 1;
    const int m0 = blockIdx.x * 128;
    const long n0 = (long)blockIdx.y * 128;

    const __half* gA0 = Ahi + (long)m0 * K;
    const __half* gA1 = Alo + (long)m0 * K;
    const __half* gB0 = Bhi + n0 * Kb;
    const __half* gB1 = Blo + n0 * Kb;

    const int lrow0 = tid >> 2, lcol = tid & 3;
    const int lrow1 = lrow0 + 64;

    // conv B-row geometry (pix = img*288 + l*3 + s)
    int l0 = 0, s0 = 0, l1 = 0, s1 = 0;
    if (conv) {
        const int p0 = (int)n0 + lrow0, p1 = (int)n0 + lrow1;
        s0 = p0 % 3; l0 = (p0 / 3) % 96;
        s1 = p1 % 3; l1 = (p1 / 3) % 96;
    }

    const int lg = lane >> 3, lr = lane & 7;
    const uint32_t aoff = (uint32_t)(((lg & 1) * 8 + lr) + wm * 32) * PITCH +
                          (lg >> 1) * 16;
    const uint32_t boff = (uint32_t)(((lg >> 1) * 8 + lr) + wn * 64) * PITCH +
                          (lg & 1) * 16;

    float acc[2][8][4];
    #pragma unroll
    for (int i = 0; i < 2; i++)
        #pragma unroll
        for (int j = 0; j < 8; j++)
            #pragma unroll
            for (int c = 0; c < 4; c++) acc[i][j][c] = 0.f;

    const int nC = K / BK;

    auto issue = [&](int kc) {
        const uint32_t so = sb + (kc & 1) * STAGE_BYTES;
        const uint32_t s0a = so + lrow0 * PITCH + lcol * 16;
        const uint32_t s1a = so + lrow1 * PITCH + lcol * 16;
        // A: linear in k
        {
            const long kb = (long)kc * BK;
            const long ga0 = (long)lrow0 * K + kb + lcol * 8;
            const long ga1 = (long)lrow1 * K + kb + lcol * 8;
            cp16(s0a + 0 * TILE_BYTES, gA0 + ga0);
            cp16(s1a + 0 * TILE_BYTES, gA0 + ga1);
            cp16(s0a + 1 * TILE_BYTES, gA1 + ga0);
            cp16(s1a + 1 * TILE_BYTES, gA1 + ga1);
        }
        // B: shifted view for conv, linear otherwise
        if (conv) {
            const int t = kc >> 4;                // tap 0..8
            const int dlm = t / 3 - 1, dsm = t % 3 - 1;
            const int koff = (kc & 15) * 32 + lcol * 8;
            const long rs = (long)(t - 4) * Kb;
            const int v0 = ((unsigned)(l0 + dlm) < 96u &&
                            (unsigned)(s0 + dsm) < 3u) ? 16 : 0;
            const int v1 = ((unsigned)(l1 + dlm) < 96u &&
                            (unsigned)(s1 + dsm) < 3u) ? 16 : 0;
            const long gb0 = (long)lrow0 * Kb + rs + koff;
            const long gb1 = (long)lrow1 * Kb + rs + koff;
            cp16p(s0a + 2 * TILE_BYTES, gB0 + gb0, v0);
            cp16p(s1a + 2 * TILE_BYTES, gB0 + gb1, v1);
            cp16p(s0a + 3 * TILE_BYTES, gB1 + gb0, v0);
            cp16p(s1a + 3 * TILE_BYTES, gB1 + gb1, v1);
        } else {
            const long kb = (long)kc * BK;
            const long gb0 = (long)lrow0 * Kb + kb + lcol * 8;
            const long gb1 = (long)lrow1 * Kb + kb + lcol * 8;
            cp16(s0a + 2 * TILE_BYTES, gB0 + gb0);
            cp16(s1a + 2 * TILE_BYTES, gB0 + gb1);
            cp16(s0a + 3 * TILE_BYTES, gB1 + gb0);
            cp16(s1a + 3 * TILE_BYTES, gB1 + gb1);
        }
        asm volatile("cp.async.commit_group;" ::: "memory");
    };

    issue(0);
    for (int kc = 0; kc < nC; kc++) {
        if (kc + 1 < nC) {
            issue(kc + 1);
            asm volatile("cp.async.wait_group 1;" ::: "memory");
        } else {
            asm volatile("cp.async.wait_group 0;" ::: "memory");
        }
        __syncthreads();

        const uint32_t so = sb + (kc & 1) * STAGE_BYTES;
        #pragma unroll
        for (int ks = 0; ks < 2; ks++) {
            uint32_t ah[2][4], al[2][4];
            const uint32_t ab = so + aoff + ks * 32;
            ldsm_x4(ah[0], ab);
            ldsm_x4(ah[1], ab + 16 * PITCH);
            ldsm_x4(al[0], ab + TILE_BYTES);
            ldsm_x4(al[1], ab + TILE_BYTES + 16 * PITCH);
            const uint32_t bb = so + 2 * TILE_BYTES + boff + ks * 32;
            #pragma unroll
            for (int p = 0; p < 4; p++) {
                uint32_t bh[4], bl[4];
                ldsm_x4(bh, bb + p * 16 * PITCH);
                ldsm_x4(bl, bb + p * 16 * PITCH + TILE_BYTES);
                #pragma unroll
                for (int mi = 0; mi < 2; mi++) {
                    mma16816(acc[mi][2 * p],     ah[mi], bh);
                    mma16816(acc[mi][2 * p],     ah[mi], bl);
                    mma16816(acc[mi][2 * p],     al[mi], bh);
                    mma16816(acc[mi][2 * p + 1], ah[mi], bh + 2);
                    mma16816(acc[mi][2 * p + 1], ah[mi], bl + 2);
                    mma16816(acc[mi][2 * p + 1], al[mi], bh + 2);
                }
            }
        }
        __syncthreads();
    }

    // ---------------- epilogue -------------------------------------------
    const int mrow = m0 + wm * 32 + (lane >> 2);
    const int nrow = wn * 64 + 2 * (lane & 3);
    #pragma unroll
    for (int mi = 0; mi < 2; mi++) {
        #pragma unroll
        for (int nj = 0; nj < 8; nj++) {
            #pragma unroll
            for (int ci = 0; ci < 4; ci++) {
                const int m = mrow + mi * 16 + (ci >> 1) * 8;
                const long pix = n0 + nrow + nj * 8 + (ci & 1);
                float v = acc[mi][nj][ci];
                if (mode == 3 || mode == 4) v = fmaxf(v + bias[m], 0.f);
                if (mode == 1 || mode == 3) {
                    split_g(v, outHi, outLo, pix * 512 + m);
                } else if (mode == 4) {       // NCHW scatter (convDU geometry)
                    int img = (int)(pix / 288);
                    int rem = (int)(pix - (long)img * 288);
                    int l = rem / 3, s = rem - l * 3;
                    int nb = img >> 5, ck = img & 31;
                    int h = ck * 3 + s;
                    outF[(((long)nb * 512 + m) * 96 + h) * 96 + l] = v;
                } else if (mode == 5) {       // split + H-shuffle -> LR act
                    int p = (int)pix;
                    int n = p / 2304, rem = p - n * 2304;
                    int h = rem / 48, w = rem - h * 48;
                    int h2 = 2 * h + (m >> 9);
                    int ckW = w / 3, s = w - ckW * 3;
                    long pixLR = (long)(n * 16 + ckW) * 288 + h2 * 3 + s;
                    split_g(v, outHi, outLo, pixLR * 512 + (m & 511));
                } else {                      // mode 6: split + W-shuffle -> DU act
                    int p = (int)pix;
                    int img = p / 288, rem = p - img * 288;
                    int h2 = rem / 3, s = rem - h2 * 3;
                    int n = img >> 4, ckW = img & 15;
                    int w = ckW * 3 + s;
                    int w2 = 2 * w + (m >> 9);
                    int ckH = h2 / 3, sH = h2 - ckH * 3;
                    long pixDU = (long)(n * 32 + ckH) * 288 + w2 * 3 + sH;
                    split_g(v, outHi, outLo, pixDU * 512 + (m & 511));
                }
            }
        }
    }
}

// ------------------------- prep kernels -----------------------------------
__global__ void splitW(const float* __restrict__ src, __half* __restrict__ hi,
                       __half* __restrict__ lo, int count) {
    int i = blockIdx.x * 256 + threadIdx.x;
    if (i < count) split_g(src[i], hi, lo, i);
}

// conv weight reorder + split: dst[co*4608 + t*512 + ci]
__global__ void splitWConv(const float* __restrict__ w, __half* __restrict__ hi,
                           __half* __restrict__ lo, int mulL, int mulS) {
    int i = blockIdx.x * 256 + threadIdx.x;
    int ci = i & 511;
    int t = (i >> 9) % 9;
    int co = i / 4608;
    int dl = t / 3, ds = t % 3;
    float v = w[(long)co * 4608 + ci * 9 + dl * mulL + ds * mulS];
    split_g(v, hi, lo, (long)co * 4608 + t * 512 + ci);
}

// x[n,c,h,w] -> B[pix(n,h,w), c] split
__global__ void gatherX(const float* __restrict__ x, __half* __restrict__ bhi,
                        __half* __restrict__ blo) {
    int i = blockIdx.x * 256 + threadIdx.x;
    int c4 = i & 511;
    int pix = i >> 9;
    int n = pix / 2304;
    int p = pix - n * 2304;
    const float* xs = x + ((long)n * 2048 + c4 * 4) * 2304 + p;
    long o = (long)pix * 2048 + c4 * 4;
    split_g(xs[0],    bhi, blo, o + 0);
    split_g(xs[2304], bhi, blo, o + 1);
    split_g(xs[4608], bhi, blo, o + 2);
    split_g(xs[6912], bhi, blo, o + 3);
}

// ---------------------------------------------------------------------------
// kernel_launch.  Inputs: x, w_channel, w_w, w_H, w_lr, b_lr, w_du, b_du
// ---------------------------------------------------------------------------
extern "C" void kernel_launch(void* const* d_in, const int* in_sizes, int n_in,
                              void* d_out, int out_size) {
    const float* x         = (const float*)d_in[0];
    const float* w_channel = (const float*)d_in[1];
    const float* w_w       = (const float*)d_in[2];
    const float* w_H       = (const float*)d_in[3];
    const float* w_lr      = (const float*)d_in[4];
    const float* b_lr      = (const float*)d_in[5];
    const float* w_du      = (const float*)d_in[6];
    const float* b_du      = (const float*)d_in[7];
    float* out = (float*)d_out;

    __half *aHi, *aLo, *bHi, *bLo, *cHi, *cLo, *B2hi, *B2lo;
    __half *wch_hi, *wch_lo, *ww_hi, *ww_lo, *wH_hi, *wH_lo;
    __half *wlr_hi, *wlr_lo, *wdu_hi, *wdu_lo;
    cudaGetSymbolAddress((void**)&aHi, g_aHi);
    cudaGetSymbolAddress((void**)&aLo, g_aLo);
    cudaGetSymbolAddress((void**)&bHi, g_bHi);
    cudaGetSymbolAddress((void**)&bLo, g_bLo);
    cudaGetSymbolAddress((void**)&cHi, g_cHi);
    cudaGetSymbolAddress((void**)&cLo, g_cLo);
    cudaGetSymbolAddress((void**)&B2hi, g_B2hi);
    cudaGetSymbolAddress((void**)&B2lo, g_B2lo);
    cudaGetSymbolAddress((void**)&wch_hi, g_wch_hi);
    cudaGetSymbolAddress((void**)&wch_lo, g_wch_lo);
    cudaGetSymbolAddress((void**)&ww_hi, g_ww_hi);
    cudaGetSymbolAddress((void**)&ww_lo, g_ww_lo);
    cudaGetSymbolAddress((void**)&wH_hi, g_wH_hi);
    cudaGetSymbolAddress((void**)&wH_lo, g_wH_lo);
    cudaGetSymbolAddress((void**)&wlr_hi, g_wlr_hi);
    cudaGetSymbolAddress((void**)&wlr_lo, g_wlr_lo);
    cudaGetSymbolAddress((void**)&wdu_hi, g_wdu_hi);
    cudaGetSymbolAddress((void**)&wdu_lo, g_wdu_lo);

    cudaFuncSetAttribute(gemm_hmma, cudaFuncAttributeMaxDynamicSharedMemorySize,
                         SMEM_TOTAL);

    // weight prep
    splitW<<<(512 * 2048) / 256, 256>>>(w_channel, wch_hi, wch_lo, 512 * 2048);
    splitW<<<(1024 * 512) / 256, 256>>>(w_w, ww_hi, ww_lo, 1024 * 512);
    splitW<<<(1024 * 512) / 256, 256>>>(w_H, wH_hi, wH_lo, 1024 * 512);
    splitWConv<<<(512 * 4608) / 256, 256>>>(w_lr, wlr_hi, wlr_lo, 3, 1);
    splitWConv<<<(512 * 4608) / 256, 256>>>(w_du, wdu_hi, wdu_lo, 1, 3);

    // stage 1: split(x) -> a [9216,2048]; y1 = w_channel @ x -> split B2
    gatherX<<<(9216 * 512) / 256, 256>>>(x, aHi, aLo);
    gemm_hmma<<<dim3(4, 72), 256, SMEM_TOTAL>>>(
        wch_hi, wch_lo, aHi, aLo, 2048, 2048, 0, 1, nullptr,
        nullptr, B2hi, B2lo);

    // stage 2: w_w @ y1, epilogue = H-shuffle + split -> LR act b [18432,512]
    gemm_hmma<<<dim3(8, 72), 256, SMEM_TOTAL>>>(
        ww_hi, ww_lo, B2hi, B2lo, 512, 512, 0, 5, nullptr,
        nullptr, bHi, bLo);

    // convLR pass 1 -> split c [18432,512]
    gemm_hmma<<<dim3(4, 144), 256, SMEM_TOTAL>>>(
        wlr_hi, wlr_lo, bHi, bLo, 4608, 512, 1, 3, b_lr,
        nullptr, cHi, cLo);

    // convLR pass 2 -> split a [18432,512]
    gemm_hmma<<<dim3(4, 144), 256, SMEM_TOTAL>>>(
        wlr_hi, wlr_lo, cHi, cLo, 4608, 512, 1, 3, b_lr,
        nullptr, aHi, aLo);

    // w_H stage: epilogue = W-shuffle + split -> DU act b [36864,512]
    gemm_hmma<<<dim3(8, 144), 256, SMEM_TOTAL>>>(
        wH_hi, wH_lo, aHi, aLo, 512, 512, 0, 6, nullptr,
        nullptr, bHi, bLo);

    // convDU pass 1 -> split a [36864,512]
    gemm_hmma<<<dim3(4, 288), 256, SMEM_TOTAL>>>(
        wdu_hi, wdu_lo, bHi, bLo, 4608, 512, 1, 3, b_du,
        nullptr, aHi, aLo);

    // convDU pass 2 -> final NCHW output
    gemm_hmma<<<dim3(4, 288), 256, SMEM_TOTAL>>>(
        wdu_hi, wdu_lo, aHi, aLo, 4608, 512, 1, 4, b_du,
        out, nullptr, nullptr);
}